// round 1
// baseline (speedup 1.0000x reference)
#include <cuda_runtime.h>
#include <math.h>

#define BB   64
#define TIN  128
#define NIN  256
#define MM   1024
#define OO   512
#define LMM  2048
#define TDEC 64
#define G3   3072   // 3*MM

// ---------------- scratch (device globals; no allocations allowed) ----------
__device__ float g_xt[TIN * BB * NIN];            // X transposed to [t][b][n]
__device__ float g_gi[TIN * BB * G3];             // precomputed input gates (reused layer0 -> layer1)
__device__ float g_seq0[TIN * BB * MM];           // encoder layer0 outputs
__device__ float g_e0A[BB * MM], g_e0B[BB * MM];  // layer0 / decoder-gru0 state ping-pong
__device__ float g_e1A[BB * MM], g_e1B[BB * MM];  // layer1 / decoder-gru1 state ping-pong
__device__ float g_yA[BB * OO], g_yB[BB * OO];    // decoder feedback ping-pong
__device__ float g_zpre[BB * LMM];                // fc1 output pre-LN
__device__ float g_z[BB * LMM];                   // post LN+gelu
__device__ float g_z2p[4 * BB * OO];              // fc2 split-K partials (deterministic)

// ---------------- utility kernels ----------------
__global__ void zero_init_kernel() {
    int i = blockIdx.x * blockDim.x + threadIdx.x;
    int stride = gridDim.x * blockDim.x;
    for (; i < BB * MM; i += stride) { g_e0A[i] = 0.f; g_e1A[i] = 0.f; }
}

__global__ void copy_y_kernel(const float* __restrict__ Y0) {
    int i = blockIdx.x * blockDim.x + threadIdx.x;
    if (i < BB * OO) g_yA[i] = Y0[i];
}

// Xt[(t*B+b)*N + n] = X[(b*TIN+t)*N + n]
__global__ void transpose_x_kernel(const float* __restrict__ X) {
    int i = blockIdx.x * blockDim.x + threadIdx.x;
    int stride = gridDim.x * blockDim.x;
    const int total = TIN * BB * NIN;
    for (; i < total; i += stride) {
        int n = i % NIN;
        int r = i / NIN;        // r = t*BB + b
        int t = r / BB;
        int b = r % BB;
        g_xt[i] = X[(b * TIN + t) * NIN + n];
    }
}

// ---------------- big GEMM:  C[R][Cn] = A[R][K] @ W[Cn][K]^T + bias ----------
// BM=128, BN=64, BK=16, 256 threads, thread tile 8x4
__global__ void __launch_bounds__(256) gemm_big_kernel(
    const float* __restrict__ A, const float* __restrict__ W,
    const float* __restrict__ bias, float* __restrict__ C,
    int K, int Cn)
{
    __shared__ float As[16][132];
    __shared__ float Bs[16][68];
    int tid = threadIdx.x;
    int tx = tid & 15;           // 0..15 -> 4 cols each
    int ty = tid >> 4;           // 0..15 -> 8 rows each
    int r0 = blockIdx.y * 128;
    int c0 = blockIdx.x * 64;

    float acc[8][4];
#pragma unroll
    for (int i = 0; i < 8; i++)
#pragma unroll
        for (int j = 0; j < 4; j++) acc[i][j] = 0.f;

    for (int k0 = 0; k0 < K; k0 += 16) {
        // A tile: 128 rows x 16 k = 512 float4, 2 per thread
#pragma unroll
        for (int i = 0; i < 2; i++) {
            int q = tid + i * 256;
            int ar = q >> 2, kq = q & 3;
            float4 v = *(const float4*)(A + (size_t)(r0 + ar) * K + k0 + kq * 4);
            As[kq * 4 + 0][ar] = v.x; As[kq * 4 + 1][ar] = v.y;
            As[kq * 4 + 2][ar] = v.z; As[kq * 4 + 3][ar] = v.w;
        }
        // W tile: 64 rows x 16 k = 256 float4, 1 per thread
        {
            int q = tid;
            int wn = q >> 2, kq = q & 3;
            float4 v = *(const float4*)(W + (size_t)(c0 + wn) * K + k0 + kq * 4);
            Bs[kq * 4 + 0][wn] = v.x; Bs[kq * 4 + 1][wn] = v.y;
            Bs[kq * 4 + 2][wn] = v.z; Bs[kq * 4 + 3][wn] = v.w;
        }
        __syncthreads();
#pragma unroll
        for (int kk = 0; kk < 16; kk++) {
            float4 a0 = *(float4*)&As[kk][ty * 8];
            float4 a1 = *(float4*)&As[kk][ty * 8 + 4];
            float4 bb = *(float4*)&Bs[kk][tx * 4];
            float a[8] = {a0.x, a0.y, a0.z, a0.w, a1.x, a1.y, a1.z, a1.w};
            float bv[4] = {bb.x, bb.y, bb.z, bb.w};
#pragma unroll
            for (int i = 0; i < 8; i++)
#pragma unroll
                for (int j = 0; j < 4; j++) acc[i][j] += a[i] * bv[j];
        }
        __syncthreads();
    }

    int c = c0 + tx * 4;
    float4 bv = *(const float4*)(bias + c);
#pragma unroll
    for (int i = 0; i < 8; i++) {
        int r = r0 + ty * 8 + i;
        float4 o;
        o.x = acc[i][0] + bv.x; o.y = acc[i][1] + bv.y;
        o.z = acc[i][2] + bv.z; o.w = acc[i][3] + bv.w;
        *(float4*)(C + (size_t)r * Cn + c) = o;
    }
}

// ---------------- encoder GRU step (gi precomputed) ----------------
// grid 128 blocks (8 cols each), 64 threads: ty in [0,8) -> 8 rows, tx in [0,8) -> 1 col
__global__ void __launch_bounds__(64) gru_step_kernel(
    const float* __restrict__ h_in, float* __restrict__ h_out,
    float* __restrict__ seq_out,
    const float* __restrict__ gi_t,           // [B][3M]
    const float* __restrict__ Whh,            // [3M][M]
    const float* __restrict__ bhh)
{
    __shared__ float Hs[16][68];
    __shared__ float Ws[3][8][17];
    int tid = threadIdx.x;
    int tx = tid & 7, ty = tid >> 3;
    int c0 = blockIdx.x * 8;
    int c = c0 + tx;

    float ar[8], az[8], an[8];
#pragma unroll
    for (int i = 0; i < 8; i++) { ar[i] = 0.f; az[i] = 0.f; an[i] = 0.f; }

    for (int k0 = 0; k0 < MM; k0 += 16) {
        // H tile: 64 rows x 16 k = 256 float4, 4 per thread
#pragma unroll
        for (int i = 0; i < 4; i++) {
            int q = tid + i * 64;
            int rr = q >> 2, kq = q & 3;
            float4 v = *(const float4*)(h_in + (size_t)rr * MM + k0 + kq * 4);
            Hs[kq * 4 + 0][rr] = v.x; Hs[kq * 4 + 1][rr] = v.y;
            Hs[kq * 4 + 2][rr] = v.z; Hs[kq * 4 + 3][rr] = v.w;
        }
        // W tile: 3 gates x 8 cols x 16 k = 96 float4
#pragma unroll
        for (int i = 0; i < 2; i++) {
            int q = tid + i * 64;
            if (q < 96) {
                int gc = q >> 2;             // 0..23
                int gg = gc >> 3, cc = gc & 7;
                int kq = q & 3;
                float4 v = *(const float4*)(Whh + (size_t)(gg * MM + c0 + cc) * MM + k0 + kq * 4);
                Ws[gg][cc][kq * 4 + 0] = v.x; Ws[gg][cc][kq * 4 + 1] = v.y;
                Ws[gg][cc][kq * 4 + 2] = v.z; Ws[gg][cc][kq * 4 + 3] = v.w;
            }
        }
        __syncthreads();
#pragma unroll
        for (int kk = 0; kk < 16; kk++) {
            float wr = Ws[0][tx][kk], wz = Ws[1][tx][kk], wn = Ws[2][tx][kk];
            float4 h0 = *(float4*)&Hs[kk][ty * 8];
            float4 h1 = *(float4*)&Hs[kk][ty * 8 + 4];
            float hv[8] = {h0.x, h0.y, h0.z, h0.w, h1.x, h1.y, h1.z, h1.w};
#pragma unroll
            for (int i = 0; i < 8; i++) {
                ar[i] += hv[i] * wr; az[i] += hv[i] * wz; an[i] += hv[i] * wn;
            }
        }
        __syncthreads();
    }

    float br = bhh[c], bz = bhh[MM + c], bn = bhh[2 * MM + c];
#pragma unroll
    for (int i = 0; i < 8; i++) {
        int rb = ty * 8 + i;
        const float* gi = gi_t + (size_t)rb * G3;
        float r = 1.f / (1.f + expf(-(gi[c] + ar[i] + br)));
        float z = 1.f / (1.f + expf(-(gi[MM + c] + az[i] + bz)));
        float n = tanhf(gi[2 * MM + c] + r * (an[i] + bn));
        float h = h_in[(size_t)rb * MM + c];
        float ho = (1.f - z) * n + z * h;
        h_out[(size_t)rb * MM + c] = ho;
        if (seq_out) seq_out[(size_t)rb * MM + c] = ho;
    }
}

// ---------------- decoder GRU step (gi computed in-kernel) ----------------
__global__ void __launch_bounds__(64) gru_dec_kernel(
    const float* __restrict__ x, int Kx,
    const float* __restrict__ h_in, float* __restrict__ h_out,
    const float* __restrict__ Wih, const float* __restrict__ bih,
    const float* __restrict__ Whh, const float* __restrict__ bhh)
{
    __shared__ float Hs[16][68];
    __shared__ float Ws[3][8][17];
    int tid = threadIdx.x;
    int tx = tid & 7, ty = tid >> 3;
    int c0 = blockIdx.x * 8;
    int c = c0 + tx;

    float ir[8], iz[8], in_[8], hr[8], hz[8], hn[8];
#pragma unroll
    for (int i = 0; i < 8; i++) { ir[i]=0.f; iz[i]=0.f; in_[i]=0.f; hr[i]=0.f; hz[i]=0.f; hn[i]=0.f; }

    // phase 1: input gates over x / Wih
    for (int k0 = 0; k0 < Kx; k0 += 16) {
#pragma unroll
        for (int i = 0; i < 4; i++) {
            int q = tid + i * 64;
            int rr = q >> 2, kq = q & 3;
            float4 v = *(const float4*)(x + (size_t)rr * Kx + k0 + kq * 4);
            Hs[kq * 4 + 0][rr] = v.x; Hs[kq * 4 + 1][rr] = v.y;
            Hs[kq * 4 + 2][rr] = v.z; Hs[kq * 4 + 3][rr] = v.w;
        }
#pragma unroll
        for (int i = 0; i < 2; i++) {
            int q = tid + i * 64;
            if (q < 96) {
                int gc = q >> 2;
                int gg = gc >> 3, cc = gc & 7;
                int kq = q & 3;
                float4 v = *(const float4*)(Wih + (size_t)(gg * MM + c0 + cc) * Kx + k0 + kq * 4);
                Ws[gg][cc][kq * 4 + 0] = v.x; Ws[gg][cc][kq * 4 + 1] = v.y;
                Ws[gg][cc][kq * 4 + 2] = v.z; Ws[gg][cc][kq * 4 + 3] = v.w;
            }
        }
        __syncthreads();
#pragma unroll
        for (int kk = 0; kk < 16; kk++) {
            float wr = Ws[0][tx][kk], wz = Ws[1][tx][kk], wn = Ws[2][tx][kk];
            float4 h0 = *(float4*)&Hs[kk][ty * 8];
            float4 h1 = *(float4*)&Hs[kk][ty * 8 + 4];
            float hv[8] = {h0.x, h0.y, h0.z, h0.w, h1.x, h1.y, h1.z, h1.w};
#pragma unroll
            for (int i = 0; i < 8; i++) {
                ir[i] += hv[i] * wr; iz[i] += hv[i] * wz; in_[i] += hv[i] * wn;
            }
        }
        __syncthreads();
    }
    // phase 2: hidden gates over h / Whh
    for (int k0 = 0; k0 < MM; k0 += 16) {
#pragma unroll
        for (int i = 0; i < 4; i++) {
            int q = tid + i * 64;
            int rr = q >> 2, kq = q & 3;
            float4 v = *(const float4*)(h_in + (size_t)rr * MM + k0 + kq * 4);
            Hs[kq * 4 + 0][rr] = v.x; Hs[kq * 4 + 1][rr] = v.y;
            Hs[kq * 4 + 2][rr] = v.z; Hs[kq * 4 + 3][rr] = v.w;
        }
#pragma unroll
        for (int i = 0; i < 2; i++) {
            int q = tid + i * 64;
            if (q < 96) {
                int gc = q >> 2;
                int gg = gc >> 3, cc = gc & 7;
                int kq = q & 3;
                float4 v = *(const float4*)(Whh + (size_t)(gg * MM + c0 + cc) * MM + k0 + kq * 4);
                Ws[gg][cc][kq * 4 + 0] = v.x; Ws[gg][cc][kq * 4 + 1] = v.y;
                Ws[gg][cc][kq * 4 + 2] = v.z; Ws[gg][cc][kq * 4 + 3] = v.w;
            }
        }
        __syncthreads();
#pragma unroll
        for (int kk = 0; kk < 16; kk++) {
            float wr = Ws[0][tx][kk], wz = Ws[1][tx][kk], wn = Ws[2][tx][kk];
            float4 h0 = *(float4*)&Hs[kk][ty * 8];
            float4 h1 = *(float4*)&Hs[kk][ty * 8 + 4];
            float hv[8] = {h0.x, h0.y, h0.z, h0.w, h1.x, h1.y, h1.z, h1.w};
#pragma unroll
            for (int i = 0; i < 8; i++) {
                hr[i] += hv[i] * wr; hz[i] += hv[i] * wz; hn[i] += hv[i] * wn;
            }
        }
        __syncthreads();
    }

    float bri = bih[c], bzi = bih[MM + c], bni = bih[2 * MM + c];
    float brh = bhh[c], bzh = bhh[MM + c], bnh = bhh[2 * MM + c];
#pragma unroll
    for (int i = 0; i < 8; i++) {
        int rb = ty * 8 + i;
        float r = 1.f / (1.f + expf(-(ir[i] + bri + hr[i] + brh)));
        float z = 1.f / (1.f + expf(-(iz[i] + bzi + hz[i] + bzh)));
        float n = tanhf(in_[i] + bni + r * (hn[i] + bnh));
        float h = h_in[(size_t)rb * MM + c];
        h_out[(size_t)rb * MM + c] = (1.f - z) * n + z * h;
    }
}

// ---------------- small GEMM for FC layers ----------------
// BM=64 (all rows), BN=32, BK=16, 64 threads, thread tile 8x4.
// PARTIAL: write into C + blockIdx.y * BB*Cn, no bias (split-K partials).
template <bool PARTIAL>
__global__ void __launch_bounds__(64) fc_gemm_kernel(
    const float* __restrict__ A, int K,
    const float* __restrict__ W, const float* __restrict__ bias,
    float* __restrict__ C, int Cn, int kPer)
{
    __shared__ float As[16][68];
    __shared__ float Ws_[16][36];
    int tid = threadIdx.x;
    int tx = tid & 7, ty = tid >> 3;
    int c0 = blockIdx.x * 32;
    int kStart = blockIdx.y * kPer;
    int kEnd = kStart + kPer;

    float acc[8][4];
#pragma unroll
    for (int i = 0; i < 8; i++)
#pragma unroll
        for (int j = 0; j < 4; j++) acc[i][j] = 0.f;

    for (int k0 = kStart; k0 < kEnd; k0 += 16) {
#pragma unroll
        for (int i = 0; i < 4; i++) {
            int q = tid + i * 64;
            int rr = q >> 2, kq = q & 3;
            float4 v = *(const float4*)(A + (size_t)rr * K + k0 + kq * 4);
            As[kq * 4 + 0][rr] = v.x; As[kq * 4 + 1][rr] = v.y;
            As[kq * 4 + 2][rr] = v.z; As[kq * 4 + 3][rr] = v.w;
        }
#pragma unroll
        for (int i = 0; i < 2; i++) {
            int q = tid + i * 64;
            int wn = q >> 2, kq = q & 3;
            float4 v = *(const float4*)(W + (size_t)(c0 + wn) * K + k0 + kq * 4);
            Ws_[kq * 4 + 0][wn] = v.x; Ws_[kq * 4 + 1][wn] = v.y;
            Ws_[kq * 4 + 2][wn] = v.z; Ws_[kq * 4 + 3][wn] = v.w;
        }
        __syncthreads();
#pragma unroll
        for (int kk = 0; kk < 16; kk++) {
            float4 a0 = *(float4*)&As[kk][ty * 8];
            float4 a1 = *(float4*)&As[kk][ty * 8 + 4];
            float4 bb = *(float4*)&Ws_[kk][tx * 4];
            float a[8] = {a0.x, a0.y, a0.z, a0.w, a1.x, a1.y, a1.z, a1.w};
            float bv[4] = {bb.x, bb.y, bb.z, bb.w};
#pragma unroll
            for (int i = 0; i < 8; i++)
#pragma unroll
                for (int j = 0; j < 4; j++) acc[i][j] += a[i] * bv[j];
        }
        __syncthreads();
    }

    int c = c0 + tx * 4;
    if (PARTIAL) {
        float* Cp = C + (size_t)blockIdx.y * BB * Cn;
#pragma unroll
        for (int i = 0; i < 8; i++) {
            int r = ty * 8 + i;
            float4 o = {acc[i][0], acc[i][1], acc[i][2], acc[i][3]};
            *(float4*)(Cp + (size_t)r * Cn + c) = o;
        }
    } else {
        float4 bv = *(const float4*)(bias + c);
#pragma unroll
        for (int i = 0; i < 8; i++) {
            int r = ty * 8 + i;
            float4 o = {acc[i][0] + bv.x, acc[i][1] + bv.y, acc[i][2] + bv.z, acc[i][3] + bv.w};
            *(float4*)(C + (size_t)r * Cn + c) = o;
        }
    }
}

// ---------------- LayerNorm + exact GELU ----------------
__global__ void __launch_bounds__(256) ln_gelu_kernel(
    const float* __restrict__ zpre, float* __restrict__ z,
    const float* __restrict__ g, const float* __restrict__ bta)
{
    int b = blockIdx.x, tid = threadIdx.x;
    float v[8];
    float s = 0.f, s2 = 0.f;
#pragma unroll
    for (int j = 0; j < 8; j++) {
        float t = zpre[(size_t)b * LMM + tid + j * 256];
        v[j] = t; s += t; s2 += t * t;
    }
    __shared__ float red[64];
#pragma unroll
    for (int o = 16; o; o >>= 1) {
        s += __shfl_down_sync(0xffffffffu, s, o);
        s2 += __shfl_down_sync(0xffffffffu, s2, o);
    }
    int w = tid >> 5, l = tid & 31;
    if (l == 0) { red[w] = s; red[32 + w] = s2; }
    __syncthreads();
    if (tid == 0) {
        float a = 0.f, a2 = 0.f;
        for (int i = 0; i < 8; i++) { a += red[i]; a2 += red[32 + i]; }
        red[0] = a; red[32] = a2;
    }
    __syncthreads();
    float mu = red[0] * (1.f / (float)LMM);
    float var = red[32] * (1.f / (float)LMM) - mu * mu;
    float rs = rsqrtf(var + 1e-5f);
#pragma unroll
    for (int j = 0; j < 8; j++) {
        int c = tid + j * 256;
        float t = (v[j] - mu) * rs * g[c] + bta[c];
        z[(size_t)b * LMM + c] = t * normcdff(t);  // exact gelu
    }
}

// ---------------- fc2 combine + logits out + softmax feedback ----------------
__global__ void __launch_bounds__(512) fc2_softmax_kernel(
    const float* __restrict__ bias, float* __restrict__ out,
    float* __restrict__ y_out, int sstep)
{
    int b = blockIdx.x, o = threadIdx.x;
    float v = g_z2p[(size_t)b * OO + o]
            + g_z2p[(size_t)BB * OO + b * OO + o]
            + g_z2p[(size_t)2 * BB * OO + b * OO + o]
            + g_z2p[(size_t)3 * BB * OO + b * OO + o]
            + bias[o];
    out[((size_t)b * TDEC + sstep) * OO + o] = v;

    __shared__ float red[16];
    __shared__ float bc;
    int w = o >> 5, l = o & 31;
    // max
    float m = v;
#pragma unroll
    for (int d = 16; d; d >>= 1) m = fmaxf(m, __shfl_down_sync(0xffffffffu, m, d));
    if (l == 0) red[w] = m;
    __syncthreads();
    if (o == 0) {
        float a = red[0];
        for (int i = 1; i < 16; i++) a = fmaxf(a, red[i]);
        bc = a;
    }
    __syncthreads();
    float e = expf(v - bc);
    // sum
    float sum = e;
#pragma unroll
    for (int d = 16; d; d >>= 1) sum += __shfl_down_sync(0xffffffffu, sum, d);
    if (l == 0) red[w] = sum;
    __syncthreads();
    if (o == 0) {
        float a = 0.f;
        for (int i = 0; i < 16; i++) a += red[i];
        bc = a;
    }
    __syncthreads();
    y_out[(size_t)b * OO + o] = e / bc;
}

// ---------------- host launch ----------------
extern "C" void kernel_launch(void* const* d_in, const int* in_sizes, int n_in,
                              void* d_out, int out_size)
{
    const float* X        = (const float*)d_in[0];
    const float* Y0       = (const float*)d_in[1];
    const float* enc_Wih0 = (const float*)d_in[2];
    const float* enc_Whh0 = (const float*)d_in[3];
    const float* enc_bih0 = (const float*)d_in[4];
    const float* enc_bhh0 = (const float*)d_in[5];
    const float* enc_Wih1 = (const float*)d_in[6];
    const float* enc_Whh1 = (const float*)d_in[7];
    const float* enc_bih1 = (const float*)d_in[8];
    const float* enc_bhh1 = (const float*)d_in[9];
    const float* dec_Wih0 = (const float*)d_in[10];
    const float* dec_Whh0 = (const float*)d_in[11];
    const float* dec_bih0 = (const float*)d_in[12];
    const float* dec_bhh0 = (const float*)d_in[13];
    const float* dec_Wih1 = (const float*)d_in[14];
    const float* dec_Whh1 = (const float*)d_in[15];
    const float* dec_bih1 = (const float*)d_in[16];
    const float* dec_bhh1 = (const float*)d_in[17];
    const float* fc1_w    = (const float*)d_in[18];
    const float* fc1_b    = (const float*)d_in[19];
    const float* ln_g     = (const float*)d_in[20];
    const float* ln_b     = (const float*)d_in[21];
    const float* fc2_w    = (const float*)d_in[22];
    const float* fc2_b    = (const float*)d_in[23];
    float* out = (float*)d_out;

    float *xt, *gi, *seq0, *e0A, *e0B, *e1A, *e1B, *yA, *yB, *zpre, *z, *z2p;
    cudaGetSymbolAddress((void**)&xt,   g_xt);
    cudaGetSymbolAddress((void**)&gi,   g_gi);
    cudaGetSymbolAddress((void**)&seq0, g_seq0);
    cudaGetSymbolAddress((void**)&e0A,  g_e0A);
    cudaGetSymbolAddress((void**)&e0B,  g_e0B);
    cudaGetSymbolAddress((void**)&e1A,  g_e1A);
    cudaGetSymbolAddress((void**)&e1B,  g_e1B);
    cudaGetSymbolAddress((void**)&yA,   g_yA);
    cudaGetSymbolAddress((void**)&yB,   g_yB);
    cudaGetSymbolAddress((void**)&zpre, g_zpre);
    cudaGetSymbolAddress((void**)&z,    g_z);
    cudaGetSymbolAddress((void**)&z2p,  g_z2p);

    // init
    zero_init_kernel<<<256, 256>>>();
    copy_y_kernel<<<(BB * OO + 255) / 256, 256>>>(Y0);
    transpose_x_kernel<<<2048, 256>>>(X);

    const int R = TIN * BB; // 8192

    // ---- encoder layer 0 ----
    gemm_big_kernel<<<dim3(G3 / 64, R / 128), 256>>>(xt, enc_Wih0, enc_bih0, gi, NIN, G3);
    for (int t = 0; t < TIN; t++) {
        const float* hi = (t & 1) ? e0B : e0A;
        float* ho       = (t & 1) ? e0A : e0B;
        gru_step_kernel<<<128, 64>>>(hi, ho, seq0 + (size_t)t * BB * MM,
                                     gi + (size_t)t * BB * G3, enc_Whh0, enc_bhh0);
    }
    // final layer0 h is in e0A (t=127 writes A)

    // ---- encoder layer 1 ----
    gemm_big_kernel<<<dim3(G3 / 64, R / 128), 256>>>(seq0, enc_Wih1, enc_bih1, gi, MM, G3);
    for (int t = 0; t < TIN; t++) {
        const float* hi = (t & 1) ? e1B : e1A;
        float* ho       = (t & 1) ? e1A : e1B;
        gru_step_kernel<<<128, 64>>>(hi, ho, nullptr,
                                     gi + (size_t)t * BB * G3, enc_Whh1, enc_bhh1);
    }
    // final layer1 h is in e1A

    // ---- decoder ----
    for (int s = 0; s < TDEC; s++) {
        const float* yin = (s & 1) ? yB : yA;
        float* yout      = (s & 1) ? yA : yB;
        const float* h0i = (s & 1) ? e0B : e0A;
        float* h0o       = (s & 1) ? e0A : e0B;
        const float* h1i = (s & 1) ? e1B : e1A;
        float* h1o       = (s & 1) ? e1A : e1B;

        gru_dec_kernel<<<128, 64>>>(yin, OO, h0i, h0o, dec_Wih0, dec_bih0, dec_Whh0, dec_bhh0);
        gru_dec_kernel<<<128, 64>>>(h0o, MM, h1i, h1o, dec_Wih1, dec_bih1, dec_Whh1, dec_bhh1);
        fc_gemm_kernel<false><<<dim3(LMM / 32, 1), 64>>>(h1o, MM, fc1_w, fc1_b, zpre, LMM, MM);
        ln_gelu_kernel<<<BB, 256>>>(zpre, z, ln_g, ln_b);
        fc_gemm_kernel<true><<<dim3(OO / 32, 4), 64>>>(z, LMM, fc2_w, nullptr, z2p, OO, LMM / 4);
        fc2_softmax_kernel<<<BB, 512>>>(fc2_b, out, yout, s);
    }
}

// round 3
// speedup vs baseline: 1.2325x; 1.2325x over previous
#include <cuda_runtime.h>
#include <math.h>

#define BB   64
#define TIN  128
#define NIN  256
#define MM   1024
#define OO   512
#define LMM  2048
#define TDEC 64
#define G3   3072   // 3*MM

// ---------------- scratch (device globals; no allocations allowed) ----------
__device__ float g_xt[TIN * BB * NIN];            // X transposed to [t][b][n]
__device__ float g_gi[TIN * BB * G3];             // precomputed input gates
__device__ float g_seq0[TIN * BB * MM];           // encoder layer0 outputs
__device__ float g_e0A[BB * MM], g_e0B[BB * MM];
__device__ float g_e1A[BB * MM], g_e1B[BB * MM];
__device__ float g_yA[BB * OO], g_yB[BB * OO];
__device__ float g_zpre[BB * LMM];
__device__ float g_z[BB * LMM];
__device__ float g_z2p[4 * BB * OO];

// ---------------- f32x2 packed-FMA helpers ----------------
__device__ __forceinline__ unsigned long long pk2(float lo, float hi) {
    unsigned long long r;
    asm("mov.b64 %0, {%1,%2};" : "=l"(r) : "f"(lo), "f"(hi));
    return r;
}
__device__ __forceinline__ void fma2(unsigned long long& d, unsigned long long a, unsigned long long b) {
    asm("fma.rn.f32x2 %0, %1, %2, %0;" : "+l"(d) : "l"(a), "l"(b));
}
__device__ __forceinline__ float2 upk(unsigned long long v) {
    float2 f;
    asm("mov.b64 {%0,%1}, %2;" : "=f"(f.x), "=f"(f.y) : "l"(v));
    return f;
}
__device__ __forceinline__ float sigf(float x) { return 1.f / (1.f + expf(-x)); }

// ---------------- utility kernels ----------------
__global__ void zero_init_kernel() {
    int i = blockIdx.x * blockDim.x + threadIdx.x;
    int stride = gridDim.x * blockDim.x;
    for (; i < BB * MM; i += stride) { g_e0A[i] = 0.f; g_e1A[i] = 0.f; }
}

__global__ void copy_y_kernel(const float* __restrict__ Y0) {
    int i = blockIdx.x * blockDim.x + threadIdx.x;
    if (i < BB * OO) g_yA[i] = Y0[i];
}

__global__ void transpose_x_kernel(const float* __restrict__ X) {
    int i = blockIdx.x * blockDim.x + threadIdx.x;
    int stride = gridDim.x * blockDim.x;
    const int total = TIN * BB * NIN;
    for (; i < total; i += stride) {
        int n = i % NIN;
        int r = i / NIN;
        int t = r / BB;
        int b = r % BB;
        g_xt[i] = X[(b * TIN + t) * NIN + n];
    }
}

// ---------------- big GEMM: C[R][Cn] = A[R][K] @ W[Cn][K]^T + bias ----------
// 128x128 tile, 256 threads, 8x8 per thread, f32x2 accumulation (col pairs)
__global__ void __launch_bounds__(256) gemm_big_kernel(
    const float* __restrict__ A, const float* __restrict__ W,
    const float* __restrict__ bias, float* __restrict__ C,
    int K, int Cn)
{
    __shared__ __align__(16) float As[16][132];
    __shared__ __align__(16) float Bs[16][132];
    int tid = threadIdx.x;
    int tx = tid & 15;           // 8 cols each
    int ty = tid >> 4;           // 8 rows each
    int r0 = blockIdx.y * 128;
    int c0 = blockIdx.x * 128;

    unsigned long long acc[8][4];
#pragma unroll
    for (int i = 0; i < 8; i++)
#pragma unroll
        for (int j = 0; j < 4; j++) acc[i][j] = 0ull;

    for (int k0 = 0; k0 < K; k0 += 16) {
#pragma unroll
        for (int i = 0; i < 2; i++) {
            int q = tid + i * 256;
            int rr = q >> 2, kq = q & 3;
            float4 v = *(const float4*)(A + (size_t)(r0 + rr) * K + k0 + kq * 4);
            As[kq * 4 + 0][rr] = v.x; As[kq * 4 + 1][rr] = v.y;
            As[kq * 4 + 2][rr] = v.z; As[kq * 4 + 3][rr] = v.w;
        }
#pragma unroll
        for (int i = 0; i < 2; i++) {
            int q = tid + i * 256;
            int wn = q >> 2, kq = q & 3;
            float4 v = *(const float4*)(W + (size_t)(c0 + wn) * K + k0 + kq * 4);
            Bs[kq * 4 + 0][wn] = v.x; Bs[kq * 4 + 1][wn] = v.y;
            Bs[kq * 4 + 2][wn] = v.z; Bs[kq * 4 + 3][wn] = v.w;
        }
        __syncthreads();
#pragma unroll
        for (int kk = 0; kk < 16; kk++) {
            float4 b0 = *(float4*)&Bs[kk][tx * 8];
            float4 b1 = *(float4*)&Bs[kk][tx * 8 + 4];
            unsigned long long bp[4] = {pk2(b0.x, b0.y), pk2(b0.z, b0.w),
                                        pk2(b1.x, b1.y), pk2(b1.z, b1.w)};
            float4 a0 = *(float4*)&As[kk][ty * 8];
            float4 a1 = *(float4*)&As[kk][ty * 8 + 4];
            float av[8] = {a0.x, a0.y, a0.z, a0.w, a1.x, a1.y, a1.z, a1.w};
#pragma unroll
            for (int i = 0; i < 8; i++) {
                unsigned long long ap = pk2(av[i], av[i]);
#pragma unroll
                for (int j = 0; j < 4; j++) fma2(acc[i][j], ap, bp[j]);
            }
        }
        __syncthreads();
    }

    int c = c0 + tx * 8;
    float4 bv0 = *(const float4*)(bias + c);
    float4 bv1 = *(const float4*)(bias + c + 4);
#pragma unroll
    for (int i = 0; i < 8; i++) {
        int r = r0 + ty * 8 + i;
        float2 p0 = upk(acc[i][0]), p1 = upk(acc[i][1]);
        float2 p2 = upk(acc[i][2]), p3 = upk(acc[i][3]);
        float4 o0 = {p0.x + bv0.x, p0.y + bv0.y, p1.x + bv0.z, p1.y + bv0.w};
        float4 o1 = {p2.x + bv1.x, p2.y + bv1.y, p3.x + bv1.z, p3.y + bv1.w};
        *(float4*)(C + (size_t)r * Cn + c) = o0;
        *(float4*)(C + (size_t)r * Cn + c + 4) = o1;
    }
}

// ---------------- fused GRU step ----------------
// grid 256 blocks (4 n-cols each), 128 threads.
// thread: p = tid&1 -> col pair (c0+2p, c0+2p+1); row = tid>>1 (0..63).
// HAS_GI: input gates precomputed in gi_t. Otherwise computed from (x, Wih, bih).
template<bool HAS_GI>
__global__ void __launch_bounds__(128) gru_fused_kernel(
    const float* __restrict__ x, int Kx,
    const float* __restrict__ Wih, const float* __restrict__ bih,
    const float* __restrict__ gi_t,
    const float* __restrict__ h_in, float* __restrict__ h_out,
    float* __restrict__ seq_out,
    const float* __restrict__ Whh, const float* __restrict__ bhh)
{
    __shared__ __align__(16) float Hs[32][72];
    __shared__ __align__(16) float Ws[3][32][4];
    int tid = threadIdx.x;
    int p = tid & 1;
    int row = tid >> 1;
    int c0 = blockIdx.x * 4;
    int cc = 2 * p;
    int c = c0 + cc;

    unsigned long long aR = 0ull, aZ = 0ull, aN = 0ull;
    unsigned long long iR = 0ull, iZ = 0ull, iN = 0ull;

    if (!HAS_GI) {
        for (int k0 = 0; k0 < Kx; k0 += 32) {
#pragma unroll
            for (int i = 0; i < 4; i++) {
                int q = tid + i * 128;
                int rr = q >> 3, kq = q & 7;
                float4 v = *(const float4*)(x + (size_t)rr * Kx + k0 + kq * 4);
                Hs[kq * 4 + 0][rr] = v.x; Hs[kq * 4 + 1][rr] = v.y;
                Hs[kq * 4 + 2][rr] = v.z; Hs[kq * 4 + 3][rr] = v.w;
            }
            if (tid < 96) {
                int gcol = tid >> 3;
                int g = gcol >> 2, lc = gcol & 3;
                int kq = tid & 7;
                float4 v = *(const float4*)(Wih + (size_t)(g * MM + c0 + lc) * Kx + k0 + kq * 4);
                Ws[g][kq * 4 + 0][lc] = v.x; Ws[g][kq * 4 + 1][lc] = v.y;
                Ws[g][kq * 4 + 2][lc] = v.z; Ws[g][kq * 4 + 3][lc] = v.w;
            }
            __syncthreads();
#pragma unroll
            for (int kk = 0; kk < 32; kk++) {
                float h = Hs[kk][row];
                unsigned long long h2 = pk2(h, h);
                unsigned long long wr = *(const unsigned long long*)&Ws[0][kk][cc];
                unsigned long long wz = *(const unsigned long long*)&Ws[1][kk][cc];
                unsigned long long wn = *(const unsigned long long*)&Ws[2][kk][cc];
                fma2(iR, h2, wr); fma2(iZ, h2, wz); fma2(iN, h2, wn);
            }
            __syncthreads();
        }
    }

    for (int k0 = 0; k0 < MM; k0 += 32) {
#pragma unroll
        for (int i = 0; i < 4; i++) {
            int q = tid + i * 128;
            int rr = q >> 3, kq = q & 7;
            float4 v = *(const float4*)(h_in + (size_t)rr * MM + k0 + kq * 4);
            Hs[kq * 4 + 0][rr] = v.x; Hs[kq * 4 + 1][rr] = v.y;
            Hs[kq * 4 + 2][rr] = v.z; Hs[kq * 4 + 3][rr] = v.w;
        }
        if (tid < 96) {
            int gcol = tid >> 3;
            int g = gcol >> 2, lc = gcol & 3;
            int kq = tid & 7;
            float4 v = *(const float4*)(Whh + (size_t)(g * MM + c0 + lc) * MM + k0 + kq * 4);
            Ws[g][kq * 4 + 0][lc] = v.x; Ws[g][kq * 4 + 1][lc] = v.y;
            Ws[g][kq * 4 + 2][lc] = v.z; Ws[g][kq * 4 + 3][lc] = v.w;
        }
        __syncthreads();
#pragma unroll
        for (int kk = 0; kk < 32; kk++) {
            float h = Hs[kk][row];
            unsigned long long h2 = pk2(h, h);
            unsigned long long wr = *(const unsigned long long*)&Ws[0][kk][cc];
            unsigned long long wz = *(const unsigned long long*)&Ws[1][kk][cc];
            unsigned long long wn = *(const unsigned long long*)&Ws[2][kk][cc];
            fma2(aR, h2, wr); fma2(aZ, h2, wz); fma2(aN, h2, wn);
        }
        __syncthreads();
    }

    float2 hr = upk(aR), hz = upk(aZ), hn = upk(aN);
    float gr0, gr1, gz0, gz1, gn0, gn1;
    if (HAS_GI) {
        const float* gi = gi_t + (size_t)row * G3;
        gr0 = gi[c];          gr1 = gi[c + 1];
        gz0 = gi[MM + c];     gz1 = gi[MM + c + 1];
        gn0 = gi[2 * MM + c]; gn1 = gi[2 * MM + c + 1];
    } else {
        float2 ir2 = upk(iR), iz2 = upk(iZ), in2 = upk(iN);
        gr0 = ir2.x + bih[c];          gr1 = ir2.y + bih[c + 1];
        gz0 = iz2.x + bih[MM + c];     gz1 = iz2.y + bih[MM + c + 1];
        gn0 = in2.x + bih[2 * MM + c]; gn1 = in2.y + bih[2 * MM + c + 1];
    }
    float br0 = bhh[c],          br1 = bhh[c + 1];
    float bz0 = bhh[MM + c],     bz1 = bhh[MM + c + 1];
    float bn0 = bhh[2 * MM + c], bn1 = bhh[2 * MM + c + 1];

    float2 hprev = *(const float2*)(h_in + (size_t)row * MM + c);

    float r0 = sigf(gr0 + hr.x + br0);
    float r1 = sigf(gr1 + hr.y + br1);
    float z0 = sigf(gz0 + hz.x + bz0);
    float z1 = sigf(gz1 + hz.y + bz1);
    float n0 = tanhf(gn0 + r0 * (hn.x + bn0));
    float n1 = tanhf(gn1 + r1 * (hn.y + bn1));
    float2 ho;
    ho.x = (1.f - z0) * n0 + z0 * hprev.x;
    ho.y = (1.f - z1) * n1 + z1 * hprev.y;
    *(float2*)(h_out + (size_t)row * MM + c) = ho;
    if (seq_out) *(float2*)(seq_out + (size_t)row * MM + c) = ho;
}

// ---------------- FC GEMM (64 rows), f32x2 ----------------
// 8 cols/block, 128 threads: tx = tid&3 -> col pair; rg = tid>>2 -> rows rg, rg+32
template <bool PARTIAL>
__global__ void __launch_bounds__(128) fc_gemm_kernel(
    const float* __restrict__ A, int K,
    const float* __restrict__ W, const float* __restrict__ bias,
    float* __restrict__ C, int Cn, int kPer)
{
    __shared__ __align__(16) float As_[32][72];
    __shared__ __align__(16) float Ws_[32][8];
    int tid = threadIdx.x;
    int tx = tid & 3;
    int rg = tid >> 2;
    int c0 = blockIdx.x * 8;
    int kStart = blockIdx.y * kPer;
    int kEnd = kStart + kPer;

    unsigned long long acc0 = 0ull, acc1 = 0ull;

    for (int k0 = kStart; k0 < kEnd; k0 += 32) {
#pragma unroll
        for (int i = 0; i < 4; i++) {
            int q = tid + i * 128;
            int rr = q >> 3, kq = q & 7;
            float4 v = *(const float4*)(A + (size_t)rr * K + k0 + kq * 4);
            As_[kq * 4 + 0][rr] = v.x; As_[kq * 4 + 1][rr] = v.y;
            As_[kq * 4 + 2][rr] = v.z; As_[kq * 4 + 3][rr] = v.w;
        }
        if (tid < 64) {
            int ccw = tid >> 3;
            int kq = tid & 7;
            float4 v = *(const float4*)(W + (size_t)(c0 + ccw) * K + k0 + kq * 4);
            Ws_[kq * 4 + 0][ccw] = v.x; Ws_[kq * 4 + 1][ccw] = v.y;
            Ws_[kq * 4 + 2][ccw] = v.z; Ws_[kq * 4 + 3][ccw] = v.w;
        }
        __syncthreads();
#pragma unroll
        for (int kk = 0; kk < 32; kk++) {
            unsigned long long wp = *(const unsigned long long*)&Ws_[kk][2 * tx];
            float h0 = As_[kk][rg];
            float h1 = As_[kk][rg + 32];
            fma2(acc0, pk2(h0, h0), wp);
            fma2(acc1, pk2(h1, h1), wp);
        }
        __syncthreads();
    }

    int c = c0 + 2 * tx;
    float2 p0 = upk(acc0), p1 = upk(acc1);
    if (PARTIAL) {
        float* Cp = C + (size_t)blockIdx.y * BB * Cn;
        *(float2*)(Cp + (size_t)rg * Cn + c) = p0;
        *(float2*)(Cp + (size_t)(rg + 32) * Cn + c) = p1;
    } else {
        float b0 = bias[c], b1 = bias[c + 1];
        float2 o0 = {p0.x + b0, p0.y + b1};
        float2 o1 = {p1.x + b0, p1.y + b1};
        *(float2*)(C + (size_t)rg * Cn + c) = o0;
        *(float2*)(C + (size_t)(rg + 32) * Cn + c) = o1;
    }
}

// ---------------- LayerNorm + exact GELU ----------------
__global__ void __launch_bounds__(256) ln_gelu_kernel(
    const float* __restrict__ zpre, float* __restrict__ z,
    const float* __restrict__ g, const float* __restrict__ bta)
{
    int b = blockIdx.x, tid = threadIdx.x;
    float v[8];
    float s = 0.f, s2 = 0.f;
#pragma unroll
    for (int j = 0; j < 8; j++) {
        float t = zpre[(size_t)b * LMM + tid + j * 256];
        v[j] = t; s += t; s2 += t * t;
    }
    __shared__ float red[64];
#pragma unroll
    for (int o = 16; o; o >>= 1) {
        s += __shfl_down_sync(0xffffffffu, s, o);
        s2 += __shfl_down_sync(0xffffffffu, s2, o);
    }
    int w = tid >> 5, l = tid & 31;
    if (l == 0) { red[w] = s; red[32 + w] = s2; }
    __syncthreads();
    if (tid == 0) {
        float a = 0.f, a2 = 0.f;
        for (int i = 0; i < 8; i++) { a += red[i]; a2 += red[32 + i]; }
        red[0] = a; red[32] = a2;
    }
    __syncthreads();
    float mu = red[0] * (1.f / (float)LMM);
    float var = red[32] * (1.f / (float)LMM) - mu * mu;
    float rs = rsqrtf(var + 1e-5f);
#pragma unroll
    for (int j = 0; j < 8; j++) {
        int c = tid + j * 256;
        float t = (v[j] - mu) * rs * g[c] + bta[c];
        z[(size_t)b * LMM + c] = t * normcdff(t);
    }
}

// ---------------- fc2 combine + logits out + softmax feedback ----------------
__global__ void __launch_bounds__(512) fc2_softmax_kernel(
    const float* __restrict__ bias, float* __restrict__ out,
    float* __restrict__ y_out, int sstep)
{
    int b = blockIdx.x, o = threadIdx.x;
    float v = g_z2p[(size_t)b * OO + o]
            + g_z2p[(size_t)BB * OO + b * OO + o]
            + g_z2p[(size_t)2 * BB * OO + b * OO + o]
            + g_z2p[(size_t)3 * BB * OO + b * OO + o]
            + bias[o];
    out[((size_t)b * TDEC + sstep) * OO + o] = v;

    __shared__ float red[16];
    __shared__ float bc;
    int w = o >> 5, l = o & 31;
    float m = v;
#pragma unroll
    for (int d = 16; d; d >>= 1) m = fmaxf(m, __shfl_down_sync(0xffffffffu, m, d));
    if (l == 0) red[w] = m;
    __syncthreads();
    if (o == 0) {
        float a = red[0];
        for (int i = 1; i < 16; i++) a = fmaxf(a, red[i]);
        bc = a;
    }
    __syncthreads();
    float e = expf(v - bc);
    float sum = e;
#pragma unroll
    for (int d = 16; d; d >>= 1) sum += __shfl_down_sync(0xffffffffu, sum, d);
    if (l == 0) red[w] = sum;
    __syncthreads();
    if (o == 0) {
        float a = 0.f;
        for (int i = 0; i < 16; i++) a += red[i];
        bc = a;
    }
    __syncthreads();
    y_out[(size_t)b * OO + o] = e / bc;
}

// ---------------- host launch ----------------
extern "C" void kernel_launch(void* const* d_in, const int* in_sizes, int n_in,
                              void* d_out, int out_size)
{
    const float* X        = (const float*)d_in[0];
    const float* Y0       = (const float*)d_in[1];
    const float* enc_Wih0 = (const float*)d_in[2];
    const float* enc_Whh0 = (const float*)d_in[3];
    const float* enc_bih0 = (const float*)d_in[4];
    const float* enc_bhh0 = (const float*)d_in[5];
    const float* enc_Wih1 = (const float*)d_in[6];
    const float* enc_Whh1 = (const float*)d_in[7];
    const float* enc_bih1 = (const float*)d_in[8];
    const float* enc_bhh1 = (const float*)d_in[9];
    const float* dec_Wih0 = (const float*)d_in[10];
    const float* dec_Whh0 = (const float*)d_in[11];
    const float* dec_bih0 = (const float*)d_in[12];
    const float* dec_bhh0 = (const float*)d_in[13];
    const float* dec_Wih1 = (const float*)d_in[14];
    const float* dec_Whh1 = (const float*)d_in[15];
    const float* dec_bih1 = (const float*)d_in[16];
    const float* dec_bhh1 = (const float*)d_in[17];
    const float* fc1_w    = (const float*)d_in[18];
    const float* fc1_b    = (const float*)d_in[19];
    const float* ln_g     = (const float*)d_in[20];
    const float* ln_b     = (const float*)d_in[21];
    const float* fc2_w    = (const float*)d_in[22];
    const float* fc2_b    = (const float*)d_in[23];
    float* out = (float*)d_out;

    float *xt, *gi, *seq0, *e0A, *e0B, *e1A, *e1B, *yA, *yB, *zpre, *z, *z2p;
    cudaGetSymbolAddress((void**)&xt,   g_xt);
    cudaGetSymbolAddress((void**)&gi,   g_gi);
    cudaGetSymbolAddress((void**)&seq0, g_seq0);
    cudaGetSymbolAddress((void**)&e0A,  g_e0A);
    cudaGetSymbolAddress((void**)&e0B,  g_e0B);
    cudaGetSymbolAddress((void**)&e1A,  g_e1A);
    cudaGetSymbolAddress((void**)&e1B,  g_e1B);
    cudaGetSymbolAddress((void**)&yA,   g_yA);
    cudaGetSymbolAddress((void**)&yB,   g_yB);
    cudaGetSymbolAddress((void**)&zpre, g_zpre);
    cudaGetSymbolAddress((void**)&z,    g_z);
    cudaGetSymbolAddress((void**)&z2p,  g_z2p);

    zero_init_kernel<<<256, 256>>>();
    copy_y_kernel<<<(BB * OO + 255) / 256, 256>>>(Y0);
    transpose_x_kernel<<<2048, 256>>>(X);

    const int R = TIN * BB; // 8192

    // ---- encoder layer 0 ----
    gemm_big_kernel<<<dim3(G3 / 128, R / 128), 256>>>(xt, enc_Wih0, enc_bih0, gi, NIN, G3);
    for (int t = 0; t < TIN; t++) {
        const float* hi = (t & 1) ? e0B : e0A;
        float* ho       = (t & 1) ? e0A : e0B;
        gru_fused_kernel<true><<<256, 128>>>(nullptr, 0, nullptr, nullptr,
                                             gi + (size_t)t * BB * G3,
                                             hi, ho, seq0 + (size_t)t * BB * MM,
                                             enc_Whh0, enc_bhh0);
    }

    // ---- encoder layer 1 ----
    gemm_big_kernel<<<dim3(G3 / 128, R / 128), 256>>>(seq0, enc_Wih1, enc_bih1, gi, MM, G3);
    for (int t = 0; t < TIN; t++) {
        const float* hi = (t & 1) ? e1B : e1A;
        float* ho       = (t & 1) ? e1A : e1B;
        gru_fused_kernel<true><<<256, 128>>>(nullptr, 0, nullptr, nullptr,
                                             gi + (size_t)t * BB * G3,
                                             hi, ho, nullptr,
                                             enc_Whh1, enc_bhh1);
    }

    // ---- decoder ----
    for (int s = 0; s < TDEC; s++) {
        const float* yin = (s & 1) ? yB : yA;
        float* yout      = (s & 1) ? yA : yB;
        const float* h0i = (s & 1) ? e0B : e0A;
        float* h0o       = (s & 1) ? e0A : e0B;
        const float* h1i = (s & 1) ? e1B : e1A;
        float* h1o       = (s & 1) ? e1A : e1B;

        gru_fused_kernel<false><<<256, 128>>>(yin, OO, dec_Wih0, dec_bih0, nullptr,
                                              h0i, h0o, nullptr, dec_Whh0, dec_bhh0);
        gru_fused_kernel<false><<<256, 128>>>(h0o, MM, dec_Wih1, dec_bih1, nullptr,
                                              h1i, h1o, nullptr, dec_Whh1, dec_bhh1);
        fc_gemm_kernel<false><<<dim3(LMM / 8, 1), 128>>>(h1o, MM, fc1_w, fc1_b, zpre, LMM, MM);
        ln_gelu_kernel<<<BB, 256>>>(zpre, z, ln_g, ln_b);
        fc_gemm_kernel<true><<<dim3(OO / 8, 4), 128>>>(z, LMM, fc2_w, nullptr, z2p, OO, LMM / 4);
        fc2_softmax_kernel<<<BB, 512>>>(fc2_b, out, yout, s);
    }
}